// round 14
// baseline (speedup 1.0000x reference)
#include <cuda_runtime.h>
#include <cuda_bf16.h>
#include <cstdint>

// Problem: B=2, S=2048, D=1024, H=16, Dh=64, fp32.
//
// perm8 (within each 8-col group of a contraction dim):
// pos8(i) = i<4 ? 2i : 2(i-4)+1, applied to BOTH operands -> dot invariant.
// mma frag cols {gc, gc+4} become one LDS.64.

#define B_   2
#define S_   2048
#define D_   1024
#define H_   16
#define DH_  64
#define HD_  (H_ * DH_)          // 1024
#define M_   (B_ * S_)           // 4096

#define QKV_ELEMS (B_ * S_ * HD_)

__device__ float g_q[QKV_ELEMS];      // rounded + dh-perm8
__device__ float g_k[QKV_ELEMS];      // rounded + dh-perm8
__device__ float g_v[QKV_ELEMS];      // rounded (plain)
__device__ float g_attn[QKV_ELEMS];   // rounded + he-perm8
__device__ float g_rr[QKV_ELEMS];     // rounded + D-perm8 residual
__device__ float g_wq[D_ * D_];
__device__ float g_wk[D_ * D_];
__device__ float g_wv[D_ * D_];
__device__ float g_woT[D_ * D_];      // rounded + he-perm8 Wo^T

__device__ __forceinline__ float to_tf32(float x) {
    uint32_t r;
    asm("cvt.rna.tf32.f32 %0, %1;" : "=r"(r) : "f"(x));
    return __uint_as_float(r);
}

// mma.sync m16n8k8 tf32 (fragment mapping validated R4-R13):
// A: a0=A[gr][gc] a1=A[gr+8][gc] a2=A[gr][gc+4] a3=A[gr+8][gc+4]
// B: b0=B[n=gr][k=gc] b1=B[n=gr][k=gc+4]
// C: c0=C[gr][2gc] c1=C[gr][2gc+1] c2=C[gr+8][2gc] c3=C[gr+8][2gc+1]
__device__ __forceinline__ void mma_tf32(float* d, const float* a, const float* b) {
    asm volatile(
        "mma.sync.aligned.m16n8k8.row.col.f32.tf32.tf32.f32 "
        "{%0,%1,%2,%3}, {%4,%5,%6,%7}, {%8,%9}, {%0,%1,%2,%3};"
        : "+f"(d[0]), "+f"(d[1]), "+f"(d[2]), "+f"(d[3])
        : "r"(__float_as_uint(a[0])), "r"(__float_as_uint(a[1])),
          "r"(__float_as_uint(a[2])), "r"(__float_as_uint(a[3])),
          "r"(__float_as_uint(b[0])), "r"(__float_as_uint(b[1])));
}

// ===========================================================================
// tf32 mma GEMM: C[M,N] = A[M,K] . B[N,K]^T  — R11 body (best measured).
// 128x128 tile, BK=32, 256 threads, 8 warps @ 64x32, GST=40, LDS.64 frags.
// OUT_MODE: 0 = plain store, 1 = tf32-rounded, 2 = rounded + N-perm8.
// ===========================================================================
#define GST 40

template <int OUT_MODE>
__device__ __forceinline__ void gemm_body(
    const float* __restrict__ A, const float* __restrict__ B,
    float* __restrict__ C, int M, int N, int K)
{
    __shared__ float As[128 * GST];
    __shared__ float Bs[128 * GST];

    const int tid = threadIdx.x;
    const int lane = tid & 31;
    const int w = tid >> 5;
    const int wm = (w & 1) * 64;
    const int wn = (w >> 1) * 32;
    const int row0 = blockIdx.y * 128;
    const int col0 = blockIdx.x * 128;

    const int ar = tid >> 3;
    const int ac = (tid & 7) * 4;

    const float* Ap = A + (size_t)(row0 + ar) * K + ac;
    const float* Bp = B + (size_t)(col0 + ar) * K + ac;

    float4 pa[4], pb[4];
#pragma unroll
    for (int p = 0; p < 4; p++) {
        pa[p] = *(const float4*)(Ap + (size_t)p * 32 * K);
        pb[p] = *(const float4*)(Bp + (size_t)p * 32 * K);
    }

    float acc[4][4][4];
#pragma unroll
    for (int mi = 0; mi < 4; mi++)
#pragma unroll
        for (int ni = 0; ni < 4; ni++)
#pragma unroll
            for (int e = 0; e < 4; e++) acc[mi][ni][e] = 0.f;

    const int gr = lane >> 2;
    const int gc = lane & 3;
    const int iters = K / 32;

    for (int kt = 0;;) {
#pragma unroll
        for (int p = 0; p < 4; p++) {
            const int r = ar + p * 32;
            *(float4*)&As[r * GST + ac] = pa[p];
            *(float4*)&Bs[r * GST + ac] = pb[p];
        }
        __syncthreads();

        kt++;
        if (kt < iters) {
#pragma unroll
            for (int p = 0; p < 4; p++) {
                pa[p] = *(const float4*)(Ap + kt * 32 + (size_t)p * 32 * K);
                pb[p] = *(const float4*)(Bp + kt * 32 + (size_t)p * 32 * K);
            }
        }

#pragma unroll
        for (int ks = 0; ks < 4; ks++) {
            const int k0 = ks * 8 + 2 * gc;
            float af[4][4];
#pragma unroll
            for (int mi = 0; mi < 4; mi++) {
                const float2 alo = *(const float2*)&As[(wm + mi * 16 + gr) * GST + k0];
                const float2 ahi = *(const float2*)&As[(wm + mi * 16 + gr + 8) * GST + k0];
                af[mi][0] = alo.x; af[mi][1] = ahi.x;
                af[mi][2] = alo.y; af[mi][3] = ahi.y;
            }
            float bf[4][2];
#pragma unroll
            for (int ni = 0; ni < 4; ni++) {
                const float2 b2 = *(const float2*)&Bs[(wn + ni * 8 + gr) * GST + k0];
                bf[ni][0] = b2.x; bf[ni][1] = b2.y;
            }
#pragma unroll
            for (int mi = 0; mi < 4; mi++)
#pragma unroll
                for (int ni = 0; ni < 4; ni++)
                    mma_tf32(acc[mi][ni], af[mi], bf[ni]);
        }

        if (kt >= iters) break;
        __syncthreads();
    }

    const int p0 = ((gc & 1) << 2) | (gc >> 1);   // pos8(2gc); pos8(2gc+1)=p0+2
#pragma unroll
    for (int mi = 0; mi < 4; mi++) {
        const int r = row0 + wm + mi * 16 + gr;
#pragma unroll
        for (int ni = 0; ni < 4; ni++) {
            if (OUT_MODE == 2) {
                const int cb = col0 + wn + ni * 8;
                float* r0 = C + (size_t)r * N + cb;
                float* r1 = C + (size_t)(r + 8) * N + cb;
                r0[p0]     = to_tf32(acc[mi][ni][0]);
                r0[p0 + 2] = to_tf32(acc[mi][ni][1]);
                r1[p0]     = to_tf32(acc[mi][ni][2]);
                r1[p0 + 2] = to_tf32(acc[mi][ni][3]);
            } else {
                const int c = col0 + wn + ni * 8 + 2 * gc;
                float v0 = acc[mi][ni][0], v1 = acc[mi][ni][1];
                float v2 = acc[mi][ni][2], v3 = acc[mi][ni][3];
                if (OUT_MODE == 1) {
                    v0 = to_tf32(v0); v1 = to_tf32(v1);
                    v2 = to_tf32(v2); v3 = to_tf32(v3);
                }
                *(float2*)(C + (size_t)r * N + c) = make_float2(v0, v1);
                *(float2*)(C + (size_t)(r + 8) * N + c) = make_float2(v2, v3);
            }
        }
    }
}

__global__ void __launch_bounds__(256) gemm_mma_nt(
    const float* __restrict__ A, const float* __restrict__ B,
    float* __restrict__ C, int M, int N, int K)
{
    gemm_body<0>(A, B, C, M, N, K);
}

__global__ void __launch_bounds__(256) gemm_mma_qkv(
    const float* __restrict__ A,
    const float* __restrict__ Wq, const float* __restrict__ Wk,
    const float* __restrict__ Wv,
    float* __restrict__ q, float* __restrict__ k, float* __restrict__ v,
    int M, int N, int K)
{
    const int z = blockIdx.z;
    const float* Bp = (z == 0) ? Wq : (z == 1) ? Wk : Wv;
    float* Cp = (z == 0) ? q : (z == 1) ? k : v;
    if (z < 2)
        gemm_body<2>(A, Bp, Cp, M, N, K);   // q,k: rounded + dh-perm8
    else
        gemm_body<1>(A, Bp, Cp, M, N, K);   // v: rounded, plain
}

// ===========================================================================
// Merged pre-rounding + perm8 kernel: residual + Wq + Wk + Wv in ONE launch.
// ===========================================================================
#define RES_G (QKV_ELEMS / 8)      // 524288
#define W_G   (D_ * D_ / 8)        // 131072
#define ALL_G (RES_G + 3 * W_G)    // 917504

__global__ void round_perm_all(
    const float* __restrict__ res,
    const float* __restrict__ Wq, const float* __restrict__ Wk,
    const float* __restrict__ Wv,
    float* __restrict__ rr,
    float* __restrict__ wq, float* __restrict__ wk, float* __restrict__ wv)
{
    const int i = blockIdx.x * blockDim.x + threadIdx.x;
    if (i >= ALL_G) return;
    const float* in;
    float* out;
    size_t j;
    if (i < RES_G) {
        in = res; out = rr; j = i;
    } else {
        const int t = i - RES_G;
        const int z = t / W_G;
        j = t - z * W_G;
        in = (z == 0) ? Wq : (z == 1) ? Wk : Wv;
        out = (z == 0) ? wq : (z == 1) ? wk : wv;
    }
    const float4 lo = *(const float4*)(in + j * 8);
    const float4 hi = *(const float4*)(in + j * 8 + 4);
    *(float4*)(out + j * 8) =
        make_float4(to_tf32(lo.x), to_tf32(hi.x), to_tf32(lo.y), to_tf32(hi.y));
    *(float4*)(out + j * 8 + 4) =
        make_float4(to_tf32(lo.z), to_tf32(hi.z), to_tf32(lo.w), to_tf32(hi.w));
}

__global__ void transpose_round_perm(const float* __restrict__ in,
                                     float* __restrict__ out)
{
    __shared__ float t[32][33];
    const int bx = blockIdx.x * 32, by = blockIdx.y * 32;
    const int x = threadIdx.x, y = threadIdx.y;
#pragma unroll
    for (int j = 0; j < 32; j += 8)
        t[y + j][x] = in[(size_t)(by + y + j) * D_ + bx + x];
    __syncthreads();
    const int xi = x & 7;
    const int px = (x & 24) | (xi < 4 ? 2 * xi : 2 * (xi - 4) + 1);
#pragma unroll
    for (int j = 0; j < 32; j += 8)
        out[(size_t)(bx + y + j) * D_ + by + px] = to_tf32(t[x][y + j]);
}

// ===========================================================================
// Flash attention (causal) tf32 mma — R14: 128-wide KV tiles, ONE softmax
// reduction / O-rescale / l-update per 128 kv. S-phase stores RAW masked
// scores; exp is applied in the PV A-frag load (psum accumulated there).
// 128 q rows, 8 warps, LPT order. q/k dh-perm8, P perm8.
// ===========================================================================
#define KST 72            // K/V row stride
#define PST 136           // P row stride (128 kv cols + 8 pad)
#define ATTN_SMEM_FLOATS (128 * KST * 2 + 128 * PST)
#define ATTN_SMEM_BYTES  (ATTN_SMEM_FLOATS * 4)     // 143360

__global__ void __launch_bounds__(256) attn_mma(
    const float* __restrict__ Q, const float* __restrict__ K,
    const float* __restrict__ V, float* __restrict__ O)
{
    extern __shared__ float sma[];
    float* Ks = sma;                  // [128][KST] (dh-perm8 rows)
    float* Vs = sma + 128 * KST;      // [128][KST] (plain)
    float* Ps = sma + 256 * KST;      // [128][PST] (Q staging / raw scores)

    const int tid = threadIdx.x;
    const int lane = tid & 31;
    const int w = tid >> 5;
    const int gr = lane >> 2;
    const int gc = lane & 3;

    const int qt = (gridDim.x - 1) - blockIdx.x;   // LPT: heavy blocks first
    const int bh = blockIdx.y;
    const int b = bh >> 4, h = bh & 15;
    const int q0 = qt * 128;
    const size_t base = (size_t)b * S_ * HD_ + (size_t)h * DH_;

    // Stage Q (rounded + dh-perm8) into Ps, pull A-frags to registers
    {
        const int r = tid >> 4;            // 0..15
        const int c = (tid & 15) << 2;     // 0..60
#pragma unroll
        for (int rr = 0; rr < 128; rr += 16) {
            *(float4*)&Ps[(rr + r) * PST + c] =
                *(const float4*)(Q + base + (size_t)(q0 + rr + r) * HD_ + c);
        }
    }
    __syncthreads();

    float qf[8][4];
#pragma unroll
    for (int ks = 0; ks < 8; ks++) {
        const int k0 = ks * 8 + 2 * gc;
        const float2 qlo = *(const float2*)&Ps[(w * 16 + gr) * PST + k0];
        const float2 qhi = *(const float2*)&Ps[(w * 16 + gr + 8) * PST + k0];
        qf[ks][0] = qlo.x; qf[ks][1] = qhi.x;
        qf[ks][2] = qlo.y; qf[ks][3] = qhi.y;
    }
    __syncthreads();   // qf read (and cross-warp Q rows) before Ps reuse

    float o[8][4];
#pragma unroll
    for (int ni = 0; ni < 8; ni++)
#pragma unroll
        for (int e = 0; e < 4; e++) o[ni][e] = 0.f;
    float m0 = -1e30f, m1 = -1e30f, l0 = 0.f, l1 = 0.f;

    const int qg0 = q0 + w * 16 + gr;
    const int qg1 = qg0 + 8;
    const int wrow_max = q0 + w * 16 + 15;   // warp's last q row
    const int ktiles = qt + 1;               // 128-wide kv tiles
    const int p0 = ((gc & 1) << 2) | (gc >> 1);   // pos8(2gc)

    for (int kt = 0; kt < ktiles; kt++) {
        const int kv0 = kt * 128;
        __syncthreads();   // protect Ks/Vs reuse
        // Load K/V tile [128 x 64] each (pre-rounded; pure copy)
        {
            const int r = tid >> 4;
            const int c = (tid & 15) << 2;
#pragma unroll
            for (int rr = 0; rr < 128; rr += 16) {
                const int row = rr + r;
                *(float4*)&Ks[row * KST + c] =
                    *(const float4*)(K + base + (size_t)(kv0 + row) * HD_ + c);
                *(float4*)&Vs[row * KST + c] =
                    *(const float4*)(V + base + (size_t)(kv0 + row) * HD_ + c);
            }
        }
        __syncthreads();

        if (kv0 > wrow_max) continue;        // warp fully above diagonal
        const int kvmax = wrow_max - kv0;    // max unmasked local col (>=0)

        // ---- S-phase: two 64-col halves, raw masked scores -> Ps ----
        float rmax0 = -1e30f, rmax1 = -1e30f;
#pragma unroll
        for (int hh = 0; hh < 2; hh++) {
            if (hh * 64 <= kvmax) {
                float s[8][4];
#pragma unroll
                for (int ni = 0; ni < 8; ni++)
#pragma unroll
                    for (int e = 0; e < 4; e++) s[ni][e] = 0.f;

#pragma unroll
                for (int ks = 0; ks < 8; ks++) {
                    const int k0 = ks * 8 + 2 * gc;
                    float bf[8][2];
#pragma unroll
                    for (int ni = 0; ni < 8; ni++) {
                        const float2 b2 = *(const float2*)
                            &Ks[(hh * 64 + ni * 8 + gr) * KST + k0];
                        bf[ni][0] = b2.x;
                        bf[ni][1] = b2.y;
                    }
#pragma unroll
                    for (int ni = 0; ni < 8; ni++)
                        mma_tf32(s[ni], qf[ks], bf[ni]);
                }

                const float scale = 0.125f;
                if (kv0 + hh * 64 + 63 > q0 + w * 16) {
#pragma unroll
                    for (int ni = 0; ni < 8; ni++) {
                        const int c0 = kv0 + hh * 64 + ni * 8 + 2 * gc;
                        s[ni][0] = (c0     <= qg0) ? s[ni][0] * scale : -1e30f;
                        s[ni][1] = (c0 + 1 <= qg0) ? s[ni][1] * scale : -1e30f;
                        s[ni][2] = (c0     <= qg1) ? s[ni][2] * scale : -1e30f;
                        s[ni][3] = (c0 + 1 <= qg1) ? s[ni][3] * scale : -1e30f;
                    }
                } else {
#pragma unroll
                    for (int ni = 0; ni < 8; ni++)
#pragma unroll
                        for (int e = 0; e < 4; e++) s[ni][e] *= scale;
                }

                // running row maxes + raw store (perm8 positions)
                float* pr0 = &Ps[(w * 16 + gr) * PST + hh * 64];
                float* pr1 = pr0 + 8 * PST;
#pragma unroll
                for (int ni = 0; ni < 8; ni++) {
                    rmax0 = fmaxf(rmax0, fmaxf(s[ni][0], s[ni][1]));
                    rmax1 = fmaxf(rmax1, fmaxf(s[ni][2], s[ni][3]));
                    pr0[ni * 8 + p0]     = s[ni][0];
                    pr0[ni * 8 + p0 + 2] = s[ni][1];
                    pr1[ni * 8 + p0]     = s[ni][2];
                    pr1[ni * 8 + p0 + 2] = s[ni][3];
                }
            }
        }

        // ---- single softmax reduction per 128 kv ----
        rmax0 = fmaxf(rmax0, __shfl_xor_sync(0xffffffffu, rmax0, 1));
        rmax0 = fmaxf(rmax0, __shfl_xor_sync(0xffffffffu, rmax0, 2));
        rmax1 = fmaxf(rmax1, __shfl_xor_sync(0xffffffffu, rmax1, 1));
        rmax1 = fmaxf(rmax1, __shfl_xor_sync(0xffffffffu, rmax1, 2));

        const float mn0 = fmaxf(m0, rmax0);
        const float mn1 = fmaxf(m1, rmax1);
        const float corr0 = __expf(m0 - mn0);
        const float corr1 = __expf(m1 - mn1);
        m0 = mn0; m1 = mn1;

#pragma unroll
        for (int ni = 0; ni < 8; ni++) {
            o[ni][0] *= corr0; o[ni][1] *= corr0;
            o[ni][2] *= corr1; o[ni][3] *= corr1;
        }
        __syncwarp();   // raw score stores visible across the warp

        // ---- PV: exp at A-frag load, psum accumulated inline ----
        float ps0 = 0.f, ps1 = 0.f;
#pragma unroll
        for (int kb = 0; kb < 2; kb++) {
            if (kb == 1 && kvmax < 64) break;   // upper half fully masked
#pragma unroll
            for (int ks2 = 0; ks2 < 8; ks2++) {
                const int ks = kb * 8 + ks2;
                const int k0 = ks * 8 + 2 * gc;
                const float2 plo = *(const float2*)&Ps[(w * 16 + gr) * PST + k0];
                const float2 phi = *(const float2*)&Ps[(w * 16 + gr + 8) * PST + k0];
                const float e0 = __expf(plo.x - mn0);
                const float e1 = __expf(phi.x - mn1);
                const float e2 = __expf(plo.y - mn0);
                const float e3 = __expf(phi.y - mn1);
                ps0 += e0 + e2;
                ps1 += e1 + e3;
                float af[4];
                af[0] = to_tf32(e0); af[1] = to_tf32(e1);
                af[2] = to_tf32(e2); af[3] = to_tf32(e3);
                const float* v0 = &Vs[(ks * 8 + gc) * KST + gr];
                const float* v1 = &Vs[(ks * 8 + gc + 4) * KST + gr];
                float bf[8][2];
#pragma unroll
                for (int ni = 0; ni < 8; ni++) {
                    bf[ni][0] = v0[ni * 8];
                    bf[ni][1] = v1[ni * 8];
                }
#pragma unroll
                for (int ni = 0; ni < 8; ni++)
                    mma_tf32(o[ni], af, bf[ni]);
            }
        }

        ps0 += __shfl_xor_sync(0xffffffffu, ps0, 1);
        ps0 += __shfl_xor_sync(0xffffffffu, ps0, 2);
        ps1 += __shfl_xor_sync(0xffffffffu, ps1, 1);
        ps1 += __shfl_xor_sync(0xffffffffu, ps1, 2);
        l0 = l0 * corr0 + ps0;
        l1 = l1 * corr1 + ps1;
    }

    // Epilogue: rounded + he-perm8 stores (out-proj consumes as A).
    const float inv0 = 1.f / l0;
    const float inv1 = 1.f / l1;
#pragma unroll
    for (int ni = 0; ni < 8; ni++) {
        const int c = ni * 8;
        float* r0 = (float*)(O + base + (size_t)qg0 * HD_ + c);
        float* r1 = (float*)(O + base + (size_t)qg1 * HD_ + c);
        r0[p0]     = to_tf32(o[ni][0] * inv0);
        r0[p0 + 2] = to_tf32(o[ni][1] * inv0);
        r1[p0]     = to_tf32(o[ni][2] * inv1);
        r1[p0 + 2] = to_tf32(o[ni][3] * inv1);
    }
}

// ===========================================================================
// Host side
// ===========================================================================
extern "C" void kernel_launch(void* const* d_in, const int* in_sizes, int n_in,
                              void* d_out, int out_size)
{
    const float* residual = (const float*)d_in[0];
    const float* Wq = (const float*)d_in[1];
    const float* Wk = (const float*)d_in[2];
    const float* Wv = (const float*)d_in[3];
    const float* Wo = (const float*)d_in[4];
    float* out = (float*)d_out;

    float *q, *k, *v, *attn, *rr, *wq, *wk, *wv, *woT;
    cudaGetSymbolAddress((void**)&q,    g_q);
    cudaGetSymbolAddress((void**)&k,    g_k);
    cudaGetSymbolAddress((void**)&v,    g_v);
    cudaGetSymbolAddress((void**)&attn, g_attn);
    cudaGetSymbolAddress((void**)&rr,   g_rr);
    cudaGetSymbolAddress((void**)&wq,   g_wq);
    cudaGetSymbolAddress((void**)&wk,   g_wk);
    cudaGetSymbolAddress((void**)&wv,   g_wv);
    cudaGetSymbolAddress((void**)&woT,  g_woT);

    cudaFuncSetAttribute(attn_mma,
                         cudaFuncAttributeMaxDynamicSharedMemorySize,
                         ATTN_SMEM_BYTES);

    // Round + perm8 all GEMM operands (single launch) + Wo transpose
    round_perm_all<<<(ALL_G + 255) / 256, 256>>>(residual, Wq, Wk, Wv,
                                                 rr, wq, wk, wv);
    transpose_round_perm<<<dim3(32, 32), dim3(32, 8)>>>(Wo, woT);

    // Fused QKV projections (q/k dh-perm8, v plain; all rounded)
    dim3 gqkv(D_ / 128, M_ / 128, 3);
    gemm_mma_qkv<<<gqkv, 256>>>(rr, wq, wk, wv, q, k, v, M_, D_, D_);

    // Causal flash attention: 128-row CTAs, 128-wide KV tiles, LPT order
    dim3 gattn(S_ / 128, B_ * H_);   // (16, 32)
    attn_mma<<<gattn, 256, ATTN_SMEM_BYTES>>>(q, k, v, attn);

    // Output projection
    dim3 gg(D_ / 128, M_ / 128);
    gemm_mma_nt<<<gg, 256>>>(attn, woT, out, M_, D_, D_);
}

// round 16
// speedup vs baseline: 1.4250x; 1.4250x over previous
#include <cuda_runtime.h>
#include <cuda_fp16.h>
#include <cstdint>

// Problem: B=2, S=2048, D=1024, H=16, Dh=64, fp32.
// R16: R15 design (fp16 m16n8k16, f32 accum) with the loader unit-bug fixed:
// uint4 = 8 halves (16 bytes). fp16 mantissa == tf32 mantissa (10b RNE).
//
// half2-unit perm8 on each contraction dim: within a 16-half group, half2
// unit u (halves 2u,2u+1) stored at pos8(u) = u<4 ? 2u : 2(u-4)+1.
// Applied to BOTH operands -> dot invariant. mma k-frag units {gc, gc+4}
// are stored adjacent at half offset 4gc -> one LDS.64 per B-frag.

#define B_   2
#define S_   2048
#define D_   1024
#define H_   16
#define DH_  64
#define HD_  (H_ * DH_)          // 1024
#define M_   (B_ * S_)           // 4096

#define QKV_ELEMS (B_ * S_ * HD_)

__device__ __half g_q[QKV_ELEMS];      // half + dh-perm8
__device__ __half g_k[QKV_ELEMS];      // half + dh-perm8
__device__ __half g_v[QKV_ELEMS];      // half plain [b,s,he]
__device__ __half g_vT[QKV_ELEMS];     // half [b,h,e,s], s-perm8
__device__ __half g_attn[QKV_ELEMS];   // half + he-perm8
__device__ __half g_rr[QKV_ELEMS];     // half + D-perm8 residual
__device__ __half g_wq[D_ * D_];
__device__ __half g_wk[D_ * D_];
__device__ __half g_wv[D_ * D_];
__device__ __half g_woT[D_ * D_];      // half [d][he], he-perm8

// mma.sync m16n8k16 f16 (f32 accum). Thread (gr=lane>>2, gc=lane&3):
// a0=(row gr, unit gc) a1=(gr+8, gc) a2=(gr, gc+4) a3=(gr+8, gc+4)
// b0=(n=gr, unit gc) b1=(n=gr, unit gc+4)
// C: c0=C[gr][2gc] c1=C[gr][2gc+1] c2=C[gr+8][2gc] c3=C[gr+8][2gc+1]
__device__ __forceinline__ void mma_f16(float* d, const uint32_t* a,
                                        const uint32_t* b) {
    asm volatile(
        "mma.sync.aligned.m16n8k16.row.col.f32.f16.f16.f32 "
        "{%0,%1,%2,%3}, {%4,%5,%6,%7}, {%8,%9}, {%0,%1,%2,%3};"
        : "+f"(d[0]), "+f"(d[1]), "+f"(d[2]), "+f"(d[3])
        : "r"(a[0]), "r"(a[1]), "r"(a[2]), "r"(a[3]),
          "r"(b[0]), "r"(b[1]));
}

// ===========================================================================
// fp16 mma GEMM: C[M,N] = A[M,K] . B[N,K]^T   (A,B half, K-dim perm8 units)
// BK=64 halves (4 k16 steps), 128x128 tile, 256 threads, 8 warps @ 64x32.
// GSTH=80 halves (word stride 40 == 8 mod 32 -> conflict-free LDS.64 frags).
// OUT_MODE: 0 = fp32 plain, 1 = half plain, 2 = half + N-perm8.
// ===========================================================================
#define GSTH 80

template <int OUT_MODE>
__device__ __forceinline__ void gemm_body(
    const __half* __restrict__ A, const __half* __restrict__ B,
    void* __restrict__ Cv, int M, int N, int K)
{
    __shared__ __half As[128 * GSTH];
    __shared__ __half Bs[128 * GSTH];

    const int tid = threadIdx.x;
    const int lane = tid & 31;
    const int w = tid >> 5;
    const int wm = (w & 1) * 64;
    const int wn = (w >> 1) * 32;
    const int row0 = blockIdx.y * 128;
    const int col0 = blockIdx.x * 128;

    // loader: row lr, 32 halves starting at lch (= 4 x uint4 of 8 halves)
    const int lr = tid >> 1;
    const int lch = (tid & 1) * 32;

    const __half* Ap = A + (size_t)(row0 + lr) * K + lch;
    const __half* Bp = B + (size_t)(col0 + lr) * K + lch;

    uint4 pa[4], pb[4];
#pragma unroll
    for (int p = 0; p < 4; p++) {   // 4 x 8 halves = 32 halves
        pa[p] = *(const uint4*)(Ap + p * 8);
        pb[p] = *(const uint4*)(Bp + p * 8);
    }

    float acc[4][4][4];
#pragma unroll
    for (int mi = 0; mi < 4; mi++)
#pragma unroll
        for (int ni = 0; ni < 4; ni++)
#pragma unroll
            for (int e = 0; e < 4; e++) acc[mi][ni][e] = 0.f;

    const int gr = lane >> 2;
    const int gc = lane & 3;
    const int iters = K / 64;

    for (int kt = 0;;) {
#pragma unroll
        for (int p = 0; p < 4; p++) {
            *(uint4*)&As[lr * GSTH + lch + p * 8] = pa[p];
            *(uint4*)&Bs[lr * GSTH + lch + p * 8] = pb[p];
        }
        __syncthreads();

        kt++;
        if (kt < iters) {
#pragma unroll
            for (int p = 0; p < 4; p++) {
                pa[p] = *(const uint4*)(Ap + kt * 64 + p * 8);
                pb[p] = *(const uint4*)(Bp + kt * 64 + p * 8);
            }
        }

#pragma unroll
        for (int ks = 0; ks < 4; ks++) {
            const int k0h = ks * 16 + 4 * gc;   // stored units 2gc, 2gc+1
            uint32_t af[4][4];
#pragma unroll
            for (int mi = 0; mi < 4; mi++) {
                const uint2 alo = *(const uint2*)&As[(wm + mi * 16 + gr) * GSTH + k0h];
                const uint2 ahi = *(const uint2*)&As[(wm + mi * 16 + gr + 8) * GSTH + k0h];
                af[mi][0] = alo.x; af[mi][1] = ahi.x;
                af[mi][2] = alo.y; af[mi][3] = ahi.y;
            }
            uint32_t bf[4][2];
#pragma unroll
            for (int ni = 0; ni < 4; ni++) {
                const uint2 b2 = *(const uint2*)&Bs[(wn + ni * 8 + gr) * GSTH + k0h];
                bf[ni][0] = b2.x; bf[ni][1] = b2.y;
            }
#pragma unroll
            for (int mi = 0; mi < 4; mi++)
#pragma unroll
                for (int ni = 0; ni < 4; ni++)
                    mma_f16(acc[mi][ni], af[mi], bf[ni]);
        }

        if (kt >= iters) break;
        __syncthreads();
    }

#pragma unroll
    for (int mi = 0; mi < 4; mi++) {
        const int r = row0 + wm + mi * 16 + gr;
#pragma unroll
        for (int ni = 0; ni < 4; ni++) {
            if (OUT_MODE == 0) {
                float* C = (float*)Cv;
                const int c = col0 + wn + ni * 8 + 2 * gc;
                *(float2*)(C + (size_t)r * N + c) =
                    make_float2(acc[mi][ni][0], acc[mi][ni][1]);
                *(float2*)(C + (size_t)(r + 8) * N + c) =
                    make_float2(acc[mi][ni][2], acc[mi][ni][3]);
            } else {
                __half* C = (__half*)Cv;
                const __half2 h0 = __floats2half2_rn(acc[mi][ni][0], acc[mi][ni][1]);
                const __half2 h1 = __floats2half2_rn(acc[mi][ni][2], acc[mi][ni][3]);
                int c;
                if (OUT_MODE == 2) {
                    // half2 unit idx within 16-group: 4*(ni&1)+gc -> pos8 = 2gc+(ni&1)
                    c = col0 + wn + (ni >> 1) * 16 + (2 * gc + (ni & 1)) * 2;
                } else {
                    c = col0 + wn + ni * 8 + 2 * gc;
                }
                *(__half2*)(C + (size_t)r * N + c) = h0;
                *(__half2*)(C + (size_t)(r + 8) * N + c) = h1;
            }
        }
    }
}

__global__ void __launch_bounds__(256) gemm_f16_out32(
    const __half* __restrict__ A, const __half* __restrict__ B,
    float* __restrict__ C, int M, int N, int K)
{
    gemm_body<0>(A, B, C, M, N, K);
}

__global__ void __launch_bounds__(256) gemm_f16_qkv(
    const __half* __restrict__ A,
    const __half* __restrict__ Wq, const __half* __restrict__ Wk,
    const __half* __restrict__ Wv,
    __half* __restrict__ q, __half* __restrict__ k, __half* __restrict__ v,
    int M, int N, int K)
{
    const int z = blockIdx.z;
    const __half* Bp = (z == 0) ? Wq : (z == 1) ? Wk : Wv;
    __half* Cp = (z == 0) ? q : (z == 1) ? k : v;
    if (z < 2)
        gemm_body<2>(A, Bp, Cp, M, N, K);   // q,k: half + dh-perm8
    else
        gemm_body<1>(A, Bp, Cp, M, N, K);   // v: half plain
}

// ===========================================================================
// fp32 -> half conversion with half2-unit perm8 on the contraction dim.
// Position p holds unit uorder[p] = {0,4,1,5,2,6,3,7}.
// ===========================================================================
#define RES_G (QKV_ELEMS / 16)
#define W_G   (D_ * D_ / 16)
#define ALL_G (RES_G + 3 * W_G)

__device__ __forceinline__ void conv_group(const float* in, __half* out) {
    const int uorder[8] = {0, 4, 1, 5, 2, 6, 3, 7};
    __half2 h[8];
#pragma unroll
    for (int p = 0; p < 8; p++) {
        const int u = uorder[p];
        h[p] = __floats2half2_rn(in[2 * u], in[2 * u + 1]);
    }
    *(uint4*)out = *(uint4*)&h[0];
    *(uint4*)(out + 8) = *(uint4*)&h[4];
}

__global__ void convert_all(
    const float* __restrict__ res,
    const float* __restrict__ Wq, const float* __restrict__ Wk,
    const float* __restrict__ Wv,
    __half* __restrict__ rr,
    __half* __restrict__ wq, __half* __restrict__ wk, __half* __restrict__ wv)
{
    const int i = blockIdx.x * blockDim.x + threadIdx.x;
    if (i >= ALL_G) return;
    const float* in;
    __half* out;
    size_t j;
    if (i < RES_G) { in = res; out = rr; j = i; }
    else {
        const int t = i - RES_G;
        const int z = t / W_G;
        j = t - (size_t)z * W_G;
        in = (z == 0) ? Wq : (z == 1) ? Wk : Wv;
        out = (z == 0) ? wq : (z == 1) ? wk : wv;
    }
    conv_group(in + j * 16, out + j * 16);
}

// woT[d][he_perm8] = half(Wo[he][d])
__global__ void transpose_wo(const float* __restrict__ in,
                             __half* __restrict__ out)
{
    __shared__ float t[32][33];
    const int bx = blockIdx.x * 32, by = blockIdx.y * 32;   // bx: d, by: he
    const int x = threadIdx.x, y = threadIdx.y;
#pragma unroll
    for (int j = 0; j < 32; j += 8)
        t[y + j][x] = in[(size_t)(by + y + j) * D_ + bx + x];   // [he][d]
    __syncthreads();
    const int xi = x & 15;
    const int unit = xi >> 1, wb = xi & 1;
    const int pu = (unit < 4) ? 2 * unit : 2 * (unit - 4) + 1;
    const int px = (x & 16) | (pu * 2 + wb);
#pragma unroll
    for (int j = 0; j < 32; j += 8)
        out[(size_t)(bx + y + j) * D_ + by + px] = __float2half_rn(t[x][y + j]);
}

// vT[b][h][e][s_perm8] = v[b][s][h*64+e]
__global__ void transpose_v(const __half* __restrict__ v,
                            __half* __restrict__ vT)
{
    __shared__ __half t[32][33];
    const int bx = blockIdx.x * 32;   // he
    const int by = blockIdx.y * 32;   // s
    const int b = blockIdx.z;
    const int x = threadIdx.x, y = threadIdx.y;
#pragma unroll
    for (int j = 0; j < 32; j += 8)
        t[y + j][x] = v[(size_t)b * S_ * HD_ + (size_t)(by + y + j) * HD_ + bx + x];
    __syncthreads();
    const int s = by + x;
    const int si = s & 15;
    const int unit = si >> 1, wb = si & 1;
    const int pu = (unit < 4) ? 2 * unit : 2 * (unit - 4) + 1;
    const int sp = (s & ~15) | (pu * 2 + wb);
#pragma unroll
    for (int j = 0; j < 32; j += 8) {
        const int he = bx + y + j;
        const int h = he >> 6, e = he & 63;
        vT[((size_t)(b * 16 + h) * 64 + e) * S_ + sp] = t[x][y + j];
    }
}

// ===========================================================================
// Flash attention (causal) fp16 mma — R11 structure, k16 steps.
// Ks [64 kv][KSTH] (dh-perm8), Vt [64 dh][KSTH] (kv-perm8),
// Ps [128][KSTH] (Q staging / kv-perm8 P). All half. LPT block order.
// ===========================================================================
#define KSTH 80

__global__ void __launch_bounds__(256) attn_mma(
    const __half* __restrict__ Q, const __half* __restrict__ K,
    const __half* __restrict__ VT, __half* __restrict__ O)
{
    __shared__ __half Ks[64 * KSTH];
    __shared__ __half Vt[64 * KSTH];
    __shared__ __half Ps[128 * KSTH];

    const int tid = threadIdx.x;
    const int lane = tid & 31;
    const int w = tid >> 5;
    const int gr = lane >> 2;
    const int gc = lane & 3;

    const int qt = (gridDim.x - 1) - blockIdx.x;   // LPT: heavy first
    const int bh = blockIdx.y;
    const int b = bh >> 4, h = bh & 15;
    const int q0 = qt * 128;
    const size_t base = (size_t)b * S_ * HD_ + (size_t)h * DH_;
    const size_t vbase = (size_t)(b * 16 + h) * 64 * S_;

    // Stage Q (half, dh-perm8) into Ps: 128 rows x 64 halves
    {
        const int r = tid >> 1;            // 0..127
        const int ch = (tid & 1) * 32;     // halves
        const __half* src = Q + base + (size_t)(q0 + r) * HD_ + ch;
#pragma unroll
        for (int p = 0; p < 4; p++)
            *(uint4*)&Ps[r * KSTH + ch + p * 8] = *(const uint4*)(src + p * 8);
    }
    __syncthreads();

    uint32_t qf[4][4];
#pragma unroll
    for (int ks = 0; ks < 4; ks++) {
        const int k0h = ks * 16 + 4 * gc;
        const uint2 lo = *(const uint2*)&Ps[(w * 16 + gr) * KSTH + k0h];
        const uint2 hi = *(const uint2*)&Ps[(w * 16 + gr + 8) * KSTH + k0h];
        qf[ks][0] = lo.x; qf[ks][1] = hi.x;
        qf[ks][2] = lo.y; qf[ks][3] = hi.y;
    }
    __syncthreads();   // qf read before Ps reused for P

    float o[8][4];
#pragma unroll
    for (int ni = 0; ni < 8; ni++)
#pragma unroll
        for (int e = 0; e < 4; e++) o[ni][e] = 0.f;
    float m0 = -1e30f, m1 = -1e30f, l0 = 0.f, l1 = 0.f;

    const int qg0 = q0 + w * 16 + gr;
    const int qg1 = qg0 + 8;
    const int ktiles = 2 * qt + 2;

    for (int kt = 0; kt < ktiles; kt++) {
        const int kv0 = kt * 64;
        __syncthreads();
        // Load K tile [64 kv][64 dh] and V^T tile [64 dh][64 kv]
        // 256 threads: row tid>>2, 16 halves at ch = (tid&3)*16 (2 x uint4)
        {
            const int r = tid >> 2;            // 0..63
            const int ch = (tid & 3) * 16;     // halves 0,16,32,48
            const __half* ksrc = K + base + (size_t)(kv0 + r) * HD_ + ch;
            const __half* vsrc = VT + vbase + (size_t)r * S_ + kv0 + ch;
#pragma unroll
            for (int p = 0; p < 2; p++) {
                *(uint4*)&Ks[r * KSTH + ch + p * 8] = *(const uint4*)(ksrc + p * 8);
                *(uint4*)&Vt[r * KSTH + ch + p * 8] = *(const uint4*)(vsrc + p * 8);
            }
        }
        __syncthreads();

        if (kv0 > q0 + w * 16 + 15) continue;

        // ---- S = Q . K^T  (dh contraction, 4 k16 steps) ----
        float s[8][4];
#pragma unroll
        for (int ni = 0; ni < 8; ni++)
#pragma unroll
            for (int e = 0; e < 4; e++) s[ni][e] = 0.f;

#pragma unroll
        for (int ks = 0; ks < 4; ks++) {
            const int k0h = ks * 16 + 4 * gc;
            uint32_t bf[8][2];
#pragma unroll
            for (int ni = 0; ni < 8; ni++) {
                const uint2 b2 = *(const uint2*)&Ks[(ni * 8 + gr) * KSTH + k0h];
                bf[ni][0] = b2.x; bf[ni][1] = b2.y;
            }
#pragma unroll
            for (int ni = 0; ni < 8; ni++)
                mma_f16(s[ni], qf[ks], bf[ni]);
        }

        const float scale = 0.125f;
        if (kv0 + 63 > q0 + w * 16) {
#pragma unroll
            for (int ni = 0; ni < 8; ni++) {
                const int c0 = kv0 + ni * 8 + 2 * gc;
                s[ni][0] = (c0     <= qg0) ? s[ni][0] * scale : -1e30f;
                s[ni][1] = (c0 + 1 <= qg0) ? s[ni][1] * scale : -1e30f;
                s[ni][2] = (c0     <= qg1) ? s[ni][2] * scale : -1e30f;
                s[ni][3] = (c0 + 1 <= qg1) ? s[ni][3] * scale : -1e30f;
            }
        } else {
#pragma unroll
            for (int ni = 0; ni < 8; ni++)
#pragma unroll
                for (int e = 0; e < 4; e++) s[ni][e] *= scale;
        }

        // ---- online softmax ----
        float rmax0 = -1e30f, rmax1 = -1e30f;
#pragma unroll
        for (int ni = 0; ni < 8; ni++) {
            rmax0 = fmaxf(rmax0, fmaxf(s[ni][0], s[ni][1]));
            rmax1 = fmaxf(rmax1, fmaxf(s[ni][2], s[ni][3]));
        }
        rmax0 = fmaxf(rmax0, __shfl_xor_sync(0xffffffffu, rmax0, 1));
        rmax0 = fmaxf(rmax0, __shfl_xor_sync(0xffffffffu, rmax0, 2));
        rmax1 = fmaxf(rmax1, __shfl_xor_sync(0xffffffffu, rmax1, 1));
        rmax1 = fmaxf(rmax1, __shfl_xor_sync(0xffffffffu, rmax1, 2));

        const float mn0 = fmaxf(m0, rmax0);
        const float mn1 = fmaxf(m1, rmax1);
        const float corr0 = __expf(m0 - mn0);
        const float corr1 = __expf(m1 - mn1);

        float ps0 = 0.f, ps1 = 0.f;
#pragma unroll
        for (int ni = 0; ni < 8; ni++) {
            s[ni][0] = __expf(s[ni][0] - mn0);
            s[ni][1] = __expf(s[ni][1] - mn0);
            s[ni][2] = __expf(s[ni][2] - mn1);
            s[ni][3] = __expf(s[ni][3] - mn1);
            ps0 += s[ni][0] + s[ni][1];
            ps1 += s[ni][2] + s[ni][3];
        }
        ps0 += __shfl_xor_sync(0xffffffffu, ps0, 1);
        ps0 += __shfl_xor_sync(0xffffffffu, ps0, 2);
        ps1 += __shfl_xor_sync(0xffffffffu, ps1, 1);
        ps1 += __shfl_xor_sync(0xffffffffu, ps1, 2);

        l0 = l0 * corr0 + ps0;  m0 = mn0;
        l1 = l1 * corr1 + ps1;  m1 = mn1;

#pragma unroll
        for (int ni = 0; ni < 8; ni++) {
            o[ni][0] *= corr0; o[ni][1] *= corr0;
            o[ni][2] *= corr1; o[ni][3] *= corr1;
        }

        // ---- P -> Ps as half2 at kv-perm8 unit positions ----
        {
            __half* pr0 = &Ps[(w * 16 + gr) * KSTH];
            __half* pr1 = pr0 + 8 * KSTH;
#pragma unroll
            for (int ni = 0; ni < 8; ni++) {
                const int off = (ni >> 1) * 16 + (2 * gc + (ni & 1)) * 2;
                *(__half2*)(pr0 + off) = __floats2half2_rn(s[ni][0], s[ni][1]);
                *(__half2*)(pr1 + off) = __floats2half2_rn(s[ni][2], s[ni][3]);
            }
        }
        __syncwarp();

        // ---- O += P . V^T  (kv contraction, 4 k16 steps) ----
#pragma unroll
        for (int ks = 0; ks < 4; ks++) {
            const int k0h = ks * 16 + 4 * gc;
            const uint2 plo = *(const uint2*)&Ps[(w * 16 + gr) * KSTH + k0h];
            const uint2 phi = *(const uint2*)&Ps[(w * 16 + gr + 8) * KSTH + k0h];
            uint32_t af[4] = {plo.x, phi.x, plo.y, phi.y};
            uint32_t bf[8][2];
#pragma unroll
            for (int ni = 0; ni < 8; ni++) {
                const uint2 b2 = *(const uint2*)&Vt[(ni * 8 + gr) * KSTH + k0h];
                bf[ni][0] = b2.x; bf[ni][1] = b2.y;
            }
#pragma unroll
            for (int ni = 0; ni < 8; ni++)
                mma_f16(o[ni], af, bf[ni]);
        }
    }

    // Epilogue: half2 stores at he-perm8 positions (out-proj A operand)
    const float inv0 = 1.f / l0;
    const float inv1 = 1.f / l1;
#pragma unroll
    for (int ni = 0; ni < 8; ni++) {
        const int off = (ni >> 1) * 16 + (2 * gc + (ni & 1)) * 2;
        __half* r0 = O + base + (size_t)qg0 * HD_;
        __half* r1 = O + base + (size_t)qg1 * HD_;
        *(__half2*)(r0 + off) = __floats2half2_rn(o[ni][0] * inv0, o[ni][1] * inv0);
        *(__half2*)(r1 + off) = __floats2half2_rn(o[ni][2] * inv1, o[ni][3] * inv1);
    }
}

// ===========================================================================
// Host side
// ===========================================================================
extern "C" void kernel_launch(void* const* d_in, const int* in_sizes, int n_in,
                              void* d_out, int out_size)
{
    const float* residual = (const float*)d_in[0];
    const float* Wq = (const float*)d_in[1];
    const float* Wk = (const float*)d_in[2];
    const float* Wv = (const float*)d_in[3];
    const float* Wo = (const float*)d_in[4];
    float* out = (float*)d_out;

    __half *q, *k, *v, *vT, *attn, *rr, *wq, *wk, *wv, *woT;
    cudaGetSymbolAddress((void**)&q,    g_q);
    cudaGetSymbolAddress((void**)&k,    g_k);
    cudaGetSymbolAddress((void**)&v,    g_v);
    cudaGetSymbolAddress((void**)&vT,   g_vT);
    cudaGetSymbolAddress((void**)&attn, g_attn);
    cudaGetSymbolAddress((void**)&rr,   g_rr);
    cudaGetSymbolAddress((void**)&wq,   g_wq);
    cudaGetSymbolAddress((void**)&wk,   g_wk);
    cudaGetSymbolAddress((void**)&wv,   g_wv);
    cudaGetSymbolAddress((void**)&woT,  g_woT);

    // Convert + perm8 all GEMM operands; Wo transpose
    convert_all<<<(ALL_G + 255) / 256, 256>>>(residual, Wq, Wk, Wv,
                                              rr, wq, wk, wv);
    transpose_wo<<<dim3(32, 32), dim3(32, 8)>>>(Wo, woT);

    // Fused QKV projections (q/k dh-perm8 half, v plain half)
    dim3 gqkv(D_ / 128, M_ / 128, 3);
    gemm_f16_qkv<<<gqkv, 256>>>(rr, wq, wk, wv, q, k, v, M_, D_, D_);

    // V -> V^T [b,h,e,s] with s-perm8
    transpose_v<<<dim3(HD_ / 32, S_ / 32, B_), dim3(32, 8)>>>(v, vT);

    // Causal flash attention (fp16 mma, LPT order)
    dim3 gattn(S_ / 128, B_ * H_);
    attn_mma<<<gattn, 256>>>(q, k, vT, attn);

    // Output projection (fp32 out)
    dim3 gg(D_ / 128, M_ / 128);
    gemm_f16_out32<<<gg, 256>>>(attn, woT, out, M_, D_, D_);
}

// round 17
// speedup vs baseline: 1.4361x; 1.0078x over previous
#include <cuda_runtime.h>
#include <cuda_fp16.h>
#include <cstdint>

// Problem: B=2, S=2048, D=1024, H=16, Dh=64, fp32.
// R17 = R16 (fp16 m16n8k16, f32 accum) + register-prefetched K/V tiles in
// attention (R8-validated pattern). fp16 mantissa == tf32 mantissa (10b RNE).
//
// half2-unit perm8 on each contraction dim: within a 16-half group, half2
// unit u (halves 2u,2u+1) stored at pos8(u) = u<4 ? 2u : 2(u-4)+1.
// Applied to BOTH operands -> dot invariant. mma k-frag units {gc, gc+4}
// are stored adjacent at half offset 4gc -> one LDS.64 per B-frag.

#define B_   2
#define S_   2048
#define D_   1024
#define H_   16
#define DH_  64
#define HD_  (H_ * DH_)          // 1024
#define M_   (B_ * S_)           // 4096

#define QKV_ELEMS (B_ * S_ * HD_)

__device__ __half g_q[QKV_ELEMS];      // half + dh-perm8
__device__ __half g_k[QKV_ELEMS];      // half + dh-perm8
__device__ __half g_v[QKV_ELEMS];      // half plain [b,s,he]
__device__ __half g_vT[QKV_ELEMS];     // half [b,h,e,s], s-perm8
__device__ __half g_attn[QKV_ELEMS];   // half + he-perm8
__device__ __half g_rr[QKV_ELEMS];     // half + D-perm8 residual
__device__ __half g_wq[D_ * D_];
__device__ __half g_wk[D_ * D_];
__device__ __half g_wv[D_ * D_];
__device__ __half g_woT[D_ * D_];      // half [d][he], he-perm8

// mma.sync m16n8k16 f16 (f32 accum). Thread (gr=lane>>2, gc=lane&3):
// a0=(row gr, unit gc) a1=(gr+8, gc) a2=(gr, gc+4) a3=(gr+8, gc+4)
// b0=(n=gr, unit gc) b1=(n=gr, unit gc+4)
// C: c0=C[gr][2gc] c1=C[gr][2gc+1] c2=C[gr+8][2gc] c3=C[gr+8][2gc+1]
__device__ __forceinline__ void mma_f16(float* d, const uint32_t* a,
                                        const uint32_t* b) {
    asm volatile(
        "mma.sync.aligned.m16n8k16.row.col.f32.f16.f16.f32 "
        "{%0,%1,%2,%3}, {%4,%5,%6,%7}, {%8,%9}, {%0,%1,%2,%3};"
        : "+f"(d[0]), "+f"(d[1]), "+f"(d[2]), "+f"(d[3])
        : "r"(a[0]), "r"(a[1]), "r"(a[2]), "r"(a[3]),
          "r"(b[0]), "r"(b[1]));
}

// ===========================================================================
// fp16 mma GEMM: C[M,N] = A[M,K] . B[N,K]^T   (A,B half, K-dim perm8 units)
// BK=64 halves (4 k16 steps), 128x128 tile, 256 threads, 8 warps @ 64x32.
// GSTH=80 halves (word stride 40 == 8 mod 32 -> conflict-free LDS.64 frags).
// OUT_MODE: 0 = fp32 plain, 1 = half plain, 2 = half + N-perm8.
// ===========================================================================
#define GSTH 80

template <int OUT_MODE>
__device__ __forceinline__ void gemm_body(
    const __half* __restrict__ A, const __half* __restrict__ B,
    void* __restrict__ Cv, int M, int N, int K)
{
    __shared__ __half As[128 * GSTH];
    __shared__ __half Bs[128 * GSTH];

    const int tid = threadIdx.x;
    const int lane = tid & 31;
    const int w = tid >> 5;
    const int wm = (w & 1) * 64;
    const int wn = (w >> 1) * 32;
    const int row0 = blockIdx.y * 128;
    const int col0 = blockIdx.x * 128;

    const int lr = tid >> 1;
    const int lch = (tid & 1) * 32;

    const __half* Ap = A + (size_t)(row0 + lr) * K + lch;
    const __half* Bp = B + (size_t)(col0 + lr) * K + lch;

    uint4 pa[4], pb[4];
#pragma unroll
    for (int p = 0; p < 4; p++) {
        pa[p] = *(const uint4*)(Ap + p * 8);
        pb[p] = *(const uint4*)(Bp + p * 8);
    }

    float acc[4][4][4];
#pragma unroll
    for (int mi = 0; mi < 4; mi++)
#pragma unroll
        for (int ni = 0; ni < 4; ni++)
#pragma unroll
            for (int e = 0; e < 4; e++) acc[mi][ni][e] = 0.f;

    const int gr = lane >> 2;
    const int gc = lane & 3;
    const int iters = K / 64;

    for (int kt = 0;;) {
#pragma unroll
        for (int p = 0; p < 4; p++) {
            *(uint4*)&As[lr * GSTH + lch + p * 8] = pa[p];
            *(uint4*)&Bs[lr * GSTH + lch + p * 8] = pb[p];
        }
        __syncthreads();

        kt++;
        if (kt < iters) {
#pragma unroll
            for (int p = 0; p < 4; p++) {
                pa[p] = *(const uint4*)(Ap + kt * 64 + p * 8);
                pb[p] = *(const uint4*)(Bp + kt * 64 + p * 8);
            }
        }

#pragma unroll
        for (int ks = 0; ks < 4; ks++) {
            const int k0h = ks * 16 + 4 * gc;
            uint32_t af[4][4];
#pragma unroll
            for (int mi = 0; mi < 4; mi++) {
                const uint2 alo = *(const uint2*)&As[(wm + mi * 16 + gr) * GSTH + k0h];
                const uint2 ahi = *(const uint2*)&As[(wm + mi * 16 + gr + 8) * GSTH + k0h];
                af[mi][0] = alo.x; af[mi][1] = ahi.x;
                af[mi][2] = alo.y; af[mi][3] = ahi.y;
            }
            uint32_t bf[4][2];
#pragma unroll
            for (int ni = 0; ni < 4; ni++) {
                const uint2 b2 = *(const uint2*)&Bs[(wn + ni * 8 + gr) * GSTH + k0h];
                bf[ni][0] = b2.x; bf[ni][1] = b2.y;
            }
#pragma unroll
            for (int mi = 0; mi < 4; mi++)
#pragma unroll
                for (int ni = 0; ni < 4; ni++)
                    mma_f16(acc[mi][ni], af[mi], bf[ni]);
        }

        if (kt >= iters) break;
        __syncthreads();
    }

#pragma unroll
    for (int mi = 0; mi < 4; mi++) {
        const int r = row0 + wm + mi * 16 + gr;
#pragma unroll
        for (int ni = 0; ni < 4; ni++) {
            if (OUT_MODE == 0) {
                float* C = (float*)Cv;
                const int c = col0 + wn + ni * 8 + 2 * gc;
                *(float2*)(C + (size_t)r * N + c) =
                    make_float2(acc[mi][ni][0], acc[mi][ni][1]);
                *(float2*)(C + (size_t)(r + 8) * N + c) =
                    make_float2(acc[mi][ni][2], acc[mi][ni][3]);
            } else {
                __half* C = (__half*)Cv;
                const __half2 h0 = __floats2half2_rn(acc[mi][ni][0], acc[mi][ni][1]);
                const __half2 h1 = __floats2half2_rn(acc[mi][ni][2], acc[mi][ni][3]);
                int c;
                if (OUT_MODE == 2) {
                    c = col0 + wn + (ni >> 1) * 16 + (2 * gc + (ni & 1)) * 2;
                } else {
                    c = col0 + wn + ni * 8 + 2 * gc;
                }
                *(__half2*)(C + (size_t)r * N + c) = h0;
                *(__half2*)(C + (size_t)(r + 8) * N + c) = h1;
            }
        }
    }
}

__global__ void __launch_bounds__(256) gemm_f16_out32(
    const __half* __restrict__ A, const __half* __restrict__ B,
    float* __restrict__ C, int M, int N, int K)
{
    gemm_body<0>(A, B, C, M, N, K);
}

__global__ void __launch_bounds__(256) gemm_f16_qkv(
    const __half* __restrict__ A,
    const __half* __restrict__ Wq, const __half* __restrict__ Wk,
    const __half* __restrict__ Wv,
    __half* __restrict__ q, __half* __restrict__ k, __half* __restrict__ v,
    int M, int N, int K)
{
    const int z = blockIdx.z;
    const __half* Bp = (z == 0) ? Wq : (z == 1) ? Wk : Wv;
    __half* Cp = (z == 0) ? q : (z == 1) ? k : v;
    if (z < 2)
        gemm_body<2>(A, Bp, Cp, M, N, K);   // q,k: half + dh-perm8
    else
        gemm_body<1>(A, Bp, Cp, M, N, K);   // v: half plain
}

// ===========================================================================
// fp32 -> half conversion with half2-unit perm8 on the contraction dim.
// ===========================================================================
#define RES_G (QKV_ELEMS / 16)
#define W_G   (D_ * D_ / 16)
#define ALL_G (RES_G + 3 * W_G)

__device__ __forceinline__ void conv_group(const float* in, __half* out) {
    const int uorder[8] = {0, 4, 1, 5, 2, 6, 3, 7};
    __half2 h[8];
#pragma unroll
    for (int p = 0; p < 8; p++) {
        const int u = uorder[p];
        h[p] = __floats2half2_rn(in[2 * u], in[2 * u + 1]);
    }
    *(uint4*)out = *(uint4*)&h[0];
    *(uint4*)(out + 8) = *(uint4*)&h[4];
}

__global__ void convert_all(
    const float* __restrict__ res,
    const float* __restrict__ Wq, const float* __restrict__ Wk,
    const float* __restrict__ Wv,
    __half* __restrict__ rr,
    __half* __restrict__ wq, __half* __restrict__ wk, __half* __restrict__ wv)
{
    const int i = blockIdx.x * blockDim.x + threadIdx.x;
    if (i >= ALL_G) return;
    const float* in;
    __half* out;
    size_t j;
    if (i < RES_G) { in = res; out = rr; j = i; }
    else {
        const int t = i - RES_G;
        const int z = t / W_G;
        j = t - (size_t)z * W_G;
        in = (z == 0) ? Wq : (z == 1) ? Wk : Wv;
        out = (z == 0) ? wq : (z == 1) ? wk : wv;
    }
    conv_group(in + j * 16, out + j * 16);
}

// woT[d][he_perm8] = half(Wo[he][d])
__global__ void transpose_wo(const float* __restrict__ in,
                             __half* __restrict__ out)
{
    __shared__ float t[32][33];
    const int bx = blockIdx.x * 32, by = blockIdx.y * 32;
    const int x = threadIdx.x, y = threadIdx.y;
#pragma unroll
    for (int j = 0; j < 32; j += 8)
        t[y + j][x] = in[(size_t)(by + y + j) * D_ + bx + x];
    __syncthreads();
    const int xi = x & 15;
    const int unit = xi >> 1, wb = xi & 1;
    const int pu = (unit < 4) ? 2 * unit : 2 * (unit - 4) + 1;
    const int px = (x & 16) | (pu * 2 + wb);
#pragma unroll
    for (int j = 0; j < 32; j += 8)
        out[(size_t)(bx + y + j) * D_ + by + px] = __float2half_rn(t[x][y + j]);
}

// vT[b][h][e][s_perm8] = v[b][s][h*64+e]
__global__ void transpose_v(const __half* __restrict__ v,
                            __half* __restrict__ vT)
{
    __shared__ __half t[32][33];
    const int bx = blockIdx.x * 32;   // he
    const int by = blockIdx.y * 32;   // s
    const int b = blockIdx.z;
    const int x = threadIdx.x, y = threadIdx.y;
#pragma unroll
    for (int j = 0; j < 32; j += 8)
        t[y + j][x] = v[(size_t)b * S_ * HD_ + (size_t)(by + y + j) * HD_ + bx + x];
    __syncthreads();
    const int s = by + x;
    const int si = s & 15;
    const int unit = si >> 1, wb = si & 1;
    const int pu = (unit < 4) ? 2 * unit : 2 * (unit - 4) + 1;
    const int sp = (s & ~15) | (pu * 2 + wb);
#pragma unroll
    for (int j = 0; j < 32; j += 8) {
        const int he = bx + y + j;
        const int h = he >> 6, e = he & 63;
        vT[((size_t)(b * 16 + h) * 64 + e) * S_ + sp] = t[x][y + j];
    }
}

// ===========================================================================
// Flash attention (causal) fp16 mma — R16 + register-prefetched K/V tiles.
// Ks [64 kv][KSTH] (dh-perm8), Vt [64 dh][KSTH] (kv-perm8),
// Ps [128][KSTH] (Q staging / kv-perm8 P). All half. LPT block order.
// ===========================================================================
#define KSTH 80

__global__ void __launch_bounds__(256) attn_mma(
    const __half* __restrict__ Q, const __half* __restrict__ K,
    const __half* __restrict__ VT, __half* __restrict__ O)
{
    __shared__ __half Ks[64 * KSTH];
    __shared__ __half Vt[64 * KSTH];
    __shared__ __half Ps[128 * KSTH];

    const int tid = threadIdx.x;
    const int lane = tid & 31;
    const int w = tid >> 5;
    const int gr = lane >> 2;
    const int gc = lane & 3;

    const int qt = (gridDim.x - 1) - blockIdx.x;   // LPT: heavy first
    const int bh = blockIdx.y;
    const int b = bh >> 4, h = bh & 15;
    const int q0 = qt * 128;
    const size_t base = (size_t)b * S_ * HD_ + (size_t)h * DH_;
    const size_t vbase = (size_t)(b * 16 + h) * 64 * S_;

    // K/V loader geometry: row lrow = tid>>2, 16 halves at lch = (tid&3)*16
    const int lrow = tid >> 2;
    const int lch = (tid & 3) * 16;
    const __half* kbase_p = K + base + (size_t)lrow * HD_ + lch;
    const __half* vbase_p = VT + vbase + (size_t)lrow * S_ + lch;

    // Prefetch tile 0 into registers
    uint4 pk[2], pv[2];
#pragma unroll
    for (int p = 0; p < 2; p++) {
        pk[p] = *(const uint4*)(kbase_p + p * 8);
        pv[p] = *(const uint4*)(vbase_p + p * 8);
    }

    // Stage Q (half, dh-perm8) into Ps: 128 rows x 64 halves
    {
        const int r = tid >> 1;
        const int ch = (tid & 1) * 32;
        const __half* src = Q + base + (size_t)(q0 + r) * HD_ + ch;
#pragma unroll
        for (int p = 0; p < 4; p++)
            *(uint4*)&Ps[r * KSTH + ch + p * 8] = *(const uint4*)(src + p * 8);
    }
    __syncthreads();

    uint32_t qf[4][4];
#pragma unroll
    for (int ks = 0; ks < 4; ks++) {
        const int k0h = ks * 16 + 4 * gc;
        const uint2 lo = *(const uint2*)&Ps[(w * 16 + gr) * KSTH + k0h];
        const uint2 hi = *(const uint2*)&Ps[(w * 16 + gr + 8) * KSTH + k0h];
        qf[ks][0] = lo.x; qf[ks][1] = hi.x;
        qf[ks][2] = lo.y; qf[ks][3] = hi.y;
    }

    float o[8][4];
#pragma unroll
    for (int ni = 0; ni < 8; ni++)
#pragma unroll
        for (int e = 0; e < 4; e++) o[ni][e] = 0.f;
    float m0 = -1e30f, m1 = -1e30f, l0 = 0.f, l1 = 0.f;

    const int qg0 = q0 + w * 16 + gr;
    const int qg1 = qg0 + 8;
    const int ktiles = 2 * qt + 2;

    for (int kt = 0; kt < ktiles; kt++) {
        const int kv0 = kt * 64;
        __syncthreads();   // previous compute done (also covers qf/Q reads)
        // store prefetched tile kt into smem
#pragma unroll
        for (int p = 0; p < 2; p++) {
            *(uint4*)&Ks[lrow * KSTH + lch + p * 8] = pk[p];
            *(uint4*)&Vt[lrow * KSTH + lch + p * 8] = pv[p];
        }
        __syncthreads();   // tile kt visible

        // prefetch tile kt+1 (LDG overlaps compute below)
        if (kt + 1 < ktiles) {
            const int kvn = (kt + 1) * 64;
#pragma unroll
            for (int p = 0; p < 2; p++) {
                pk[p] = *(const uint4*)(kbase_p + (size_t)kvn * HD_ + p * 8);
                pv[p] = *(const uint4*)(vbase_p + kvn + p * 8);
            }
        }

        if (kv0 > q0 + w * 16 + 15) continue;

        // ---- S = Q . K^T  (dh contraction, 4 k16 steps) ----
        float s[8][4];
#pragma unroll
        for (int ni = 0; ni < 8; ni++)
#pragma unroll
            for (int e = 0; e < 4; e++) s[ni][e] = 0.f;

#pragma unroll
        for (int ks = 0; ks < 4; ks++) {
            const int k0h = ks * 16 + 4 * gc;
            uint32_t bf[8][2];
#pragma unroll
            for (int ni = 0; ni < 8; ni++) {
                const uint2 b2 = *(const uint2*)&Ks[(ni * 8 + gr) * KSTH + k0h];
                bf[ni][0] = b2.x; bf[ni][1] = b2.y;
            }
#pragma unroll
            for (int ni = 0; ni < 8; ni++)
                mma_f16(s[ni], qf[ks], bf[ni]);
        }

        const float scale = 0.125f;
        if (kv0 + 63 > q0 + w * 16) {
#pragma unroll
            for (int ni = 0; ni < 8; ni++) {
                const int c0 = kv0 + ni * 8 + 2 * gc;
                s[ni][0] = (c0     <= qg0) ? s[ni][0] * scale : -1e30f;
                s[ni][1] = (c0 + 1 <= qg0) ? s[ni][1] * scale : -1e30f;
                s[ni][2] = (c0     <= qg1) ? s[ni][2] * scale : -1e30f;
                s[ni][3] = (c0 + 1 <= qg1) ? s[ni][3] * scale : -1e30f;
            }
        } else {
#pragma unroll
            for (int ni = 0; ni < 8; ni++)
#pragma unroll
                for (int e = 0; e < 4; e++) s[ni][e] *= scale;
        }

        // ---- online softmax ----
        float rmax0 = -1e30f, rmax1 = -1e30f;
#pragma unroll
        for (int ni = 0; ni < 8; ni++) {
            rmax0 = fmaxf(rmax0, fmaxf(s[ni][0], s[ni][1]));
            rmax1 = fmaxf(rmax1, fmaxf(s[ni][2], s[ni][3]));
        }
        rmax0 = fmaxf(rmax0, __shfl_xor_sync(0xffffffffu, rmax0, 1));
        rmax0 = fmaxf(rmax0, __shfl_xor_sync(0xffffffffu, rmax0, 2));
        rmax1 = fmaxf(rmax1, __shfl_xor_sync(0xffffffffu, rmax1, 1));
        rmax1 = fmaxf(rmax1, __shfl_xor_sync(0xffffffffu, rmax1, 2));

        const float mn0 = fmaxf(m0, rmax0);
        const float mn1 = fmaxf(m1, rmax1);
        const float corr0 = __expf(m0 - mn0);
        const float corr1 = __expf(m1 - mn1);

        float ps0 = 0.f, ps1 = 0.f;
#pragma unroll
        for (int ni = 0; ni < 8; ni++) {
            s[ni][0] = __expf(s[ni][0] - mn0);
            s[ni][1] = __expf(s[ni][1] - mn0);
            s[ni][2] = __expf(s[ni][2] - mn1);
            s[ni][3] = __expf(s[ni][3] - mn1);
            ps0 += s[ni][0] + s[ni][1];
            ps1 += s[ni][2] + s[ni][3];
        }
        ps0 += __shfl_xor_sync(0xffffffffu, ps0, 1);
        ps0 += __shfl_xor_sync(0xffffffffu, ps0, 2);
        ps1 += __shfl_xor_sync(0xffffffffu, ps1, 1);
        ps1 += __shfl_xor_sync(0xffffffffu, ps1, 2);

        l0 = l0 * corr0 + ps0;  m0 = mn0;
        l1 = l1 * corr1 + ps1;  m1 = mn1;

#pragma unroll
        for (int ni = 0; ni < 8; ni++) {
            o[ni][0] *= corr0; o[ni][1] *= corr0;
            o[ni][2] *= corr1; o[ni][3] *= corr1;
        }

        // ---- P -> Ps as half2 at kv-perm8 unit positions ----
        {
            __half* pr0 = &Ps[(w * 16 + gr) * KSTH];
            __half* pr1 = pr0 + 8 * KSTH;
#pragma unroll
            for (int ni = 0; ni < 8; ni++) {
                const int off = (ni >> 1) * 16 + (2 * gc + (ni & 1)) * 2;
                *(__half2*)(pr0 + off) = __floats2half2_rn(s[ni][0], s[ni][1]);
                *(__half2*)(pr1 + off) = __floats2half2_rn(s[ni][2], s[ni][3]);
            }
        }
        __syncwarp();

        // ---- O += P . V^T  (kv contraction, 4 k16 steps) ----
#pragma unroll
        for (int ks = 0; ks < 4; ks++) {
            const int k0h = ks * 16 + 4 * gc;
            const uint2 plo = *(const uint2*)&Ps[(w * 16 + gr) * KSTH + k0h];
            const uint2 phi = *(const uint2*)&Ps[(w * 16 + gr + 8) * KSTH + k0h];
            uint32_t af[4] = {plo.x, phi.x, plo.y, phi.y};
            uint32_t bf[8][2];
#pragma unroll
            for (int ni = 0; ni < 8; ni++) {
                const uint2 b2 = *(const uint2*)&Vt[(ni * 8 + gr) * KSTH + k0h];
                bf[ni][0] = b2.x; bf[ni][1] = b2.y;
            }
#pragma unroll
            for (int ni = 0; ni < 8; ni++)
                mma_f16(o[ni], af, bf[ni]);
        }
    }

    // Epilogue: half2 stores at he-perm8 positions (out-proj A operand)
    const float inv0 = 1.f / l0;
    const float inv1 = 1.f / l1;
#pragma unroll
    for (int ni = 0; ni < 8; ni++) {
        const int off = (ni >> 1) * 16 + (2 * gc + (ni & 1)) * 2;
        __half* r0 = O + base + (size_t)qg0 * HD_;
        __half* r1 = O + base + (size_t)qg1 * HD_;
        *(__half2*)(r0 + off) = __floats2half2_rn(o[ni][0] * inv0, o[ni][1] * inv0);
        *(__half2*)(r1 + off) = __floats2half2_rn(o[ni][2] * inv1, o[ni][3] * inv1);
    }
}

// ===========================================================================
// Host side
// ===========================================================================
extern "C" void kernel_launch(void* const* d_in, const int* in_sizes, int n_in,
                              void* d_out, int out_size)
{
    const float* residual = (const float*)d_in[0];
    const float* Wq = (const float*)d_in[1];
    const float* Wk = (const float*)d_in[2];
    const float* Wv = (const float*)d_in[3];
    const float* Wo = (const float*)d_in[4];
    float* out = (float*)d_out;

    __half *q, *k, *v, *vT, *attn, *rr, *wq, *wk, *wv, *woT;
    cudaGetSymbolAddress((void**)&q,    g_q);
    cudaGetSymbolAddress((void**)&k,    g_k);
    cudaGetSymbolAddress((void**)&v,    g_v);
    cudaGetSymbolAddress((void**)&vT,   g_vT);
    cudaGetSymbolAddress((void**)&attn, g_attn);
    cudaGetSymbolAddress((void**)&rr,   g_rr);
    cudaGetSymbolAddress((void**)&wq,   g_wq);
    cudaGetSymbolAddress((void**)&wk,   g_wk);
    cudaGetSymbolAddress((void**)&wv,   g_wv);
    cudaGetSymbolAddress((void**)&woT,  g_woT);

    // Convert + perm8 all GEMM operands; Wo transpose
    convert_all<<<(ALL_G + 255) / 256, 256>>>(residual, Wq, Wk, Wv,
                                              rr, wq, wk, wv);
    transpose_wo<<<dim3(32, 32), dim3(32, 8)>>>(Wo, woT);

    // Fused QKV projections (q/k dh-perm8 half, v plain half)
    dim3 gqkv(D_ / 128, M_ / 128, 3);
    gemm_f16_qkv<<<gqkv, 256>>>(rr, wq, wk, wv, q, k, v, M_, D_, D_);

    // V -> V^T [b,h,e,s] with s-perm8
    transpose_v<<<dim3(HD_ / 32, S_ / 32, B_), dim3(32, 8)>>>(v, vT);

    // Causal flash attention (fp16 mma, reg-prefetched tiles, LPT order)
    dim3 gattn(S_ / 128, B_ * H_);
    attn_mma<<<gattn, 256>>>(q, k, vT, attn);

    // Output projection (fp32 out)
    dim3 gg(D_ / 128, M_ / 128);
    gemm_f16_out32<<<gg, 256>>>(attn, woT, out, M_, D_, D_);
}